// round 2
// baseline (speedup 1.0000x reference)
#include <cuda_runtime.h>
#include <cstdint>
#include <cstddef>

#define BB 16
#define LL 8192
#define DD 512
#define HH 8
#define HD 64
#define LN_EPS 1e-5f

#define BROWS 64
#define DSPLITS 64
#define DCHUNK (LL / DSPLITS) /* 128 */

// ---------------- scratch (device globals; no allocations) ----------------
__device__ __align__(16) float g_q[BB * DD];
__device__ __align__(16) float g_qhat[BB * HH * DD];
__device__ __align__(16) float g_c[BB * HH];
__device__ __align__(16) float g_sc[BB * HH * LL];                 // logits -> weights (in place)
__device__ __align__(16) float g_cvp[DSPLITS * BB * HH * DD];      // ctx partials per split

// ---------------- packed f32x2 helpers ----------------
__device__ __forceinline__ unsigned long long pack2(float x, float y) {
    unsigned long long r;
    asm("mov.b64 %0, {%1, %2};" : "=l"(r) : "f"(x), "f"(y));
    return r;
}
__device__ __forceinline__ void unpack2(unsigned long long v, float& x, float& y) {
    asm("mov.b64 {%0, %1}, %2;" : "=f"(x), "=f"(y) : "l"(v));
}
__device__ __forceinline__ unsigned long long ffma2u(unsigned long long a,
                                                     unsigned long long b,
                                                     unsigned long long c) {
    unsigned long long d;
    asm("fma.rn.f32x2 %0, %1, %2, %3;" : "=l"(d) : "l"(a), "l"(b), "l"(c));
    return d;
}

// ---------------- kernel A1: q = Q @ Wq + bq ----------------
__global__ void k_qproj(const float* __restrict__ Q, const float* __restrict__ Wq,
                        const float* __restrict__ bq) {
    __shared__ __align__(16) float qs[DD];
    int b = blockIdx.x, j = threadIdx.x;   // 512 threads
    qs[j] = Q[(size_t)b * DD + j];
    __syncthreads();
    float acc = bq[j];
#pragma unroll 8
    for (int d = 0; d < DD; d++) acc = fmaf(qs[d], Wq[(size_t)d * DD + j], acc);
    g_q[(size_t)b * DD + j] = acc;
}

// ---------------- kernel A2: qhat[b,h,d] = sum_hd Wk[d, h*64+hd]*q[b,h,hd]; c[b,h]=q.bk ----------------
__global__ void k_qhat(const float* __restrict__ Wk, const float* __restrict__ bk) {
    __shared__ __align__(16) float qs[DD];
    int b = blockIdx.x;
    int t = threadIdx.x;            // 256 threads
    int w = t >> 5, lane = t & 31;  // 8 warps
    for (int i = t; i < DD; i += 256) qs[i] = g_q[(size_t)b * DD + i];
    __syncthreads();

    // c[b][w] = sum_i qs[64w+i]*bk[64w+i]
    {
        float s = qs[w * HD + lane] * bk[w * HD + lane] +
                  qs[w * HD + 32 + lane] * bk[w * HD + 32 + lane];
        for (int o = 16; o > 0; o >>= 1) s += __shfl_xor_sync(0xffffffffu, s, o);
        if (lane == 0) g_c[b * HH + w] = s;
    }

    // qhat rows: warp w handles d = w, w+8, ...
    const float4* qs4 = (const float4*)qs;
    for (int d = w; d < DD; d += 8) {
        const float4* wr = (const float4*)(Wk + (size_t)d * DD);
        float p[4];
#pragma unroll
        for (int j = 0; j < 4; j++) {
            float4 a = wr[lane + 32 * j];       // cols 4*lane + 128*j .. +3
            float4 q4 = qs4[lane + 32 * j];
            p[j] = a.x * q4.x + a.y * q4.y + a.z * q4.z + a.w * q4.w;
        }
#pragma unroll
        for (int j = 0; j < 4; j++) {
            p[j] += __shfl_xor_sync(0xffffffffu, p[j], 1);
            p[j] += __shfl_xor_sync(0xffffffffu, p[j], 2);
            p[j] += __shfl_xor_sync(0xffffffffu, p[j], 4);
            p[j] += __shfl_xor_sync(0xffffffffu, p[j], 8);
        }
        if ((lane & 15) == 0) {
            int hb = lane >> 4;  // 0 or 1
#pragma unroll
            for (int j = 0; j < 4; j++)
                g_qhat[((size_t)b * HH + 2 * j + hb) * DD + d] = p[j];
        }
    }
}

// ---------------- kernel B: logits[b,h,l] = (K[b,l,:].qhat[b,h,:] + c)/4 ----------------
// Block: 256 threads = 8 warps. Warp pair (2g, 2g+1) handles rows rg=g; each warp covers
// 256 of the 512 d-columns; qhat held in registers; 9-shuffle tree reduces 8 heads.
__global__ __launch_bounds__(256, 2) void k_scores(const float* __restrict__ K) {
    __shared__ float scs[BROWS][HH];
    int b = blockIdx.y;
    int l0 = blockIdx.x * BROWS;
    int t = threadIdx.x, w = t >> 5, lane = t & 31;
    int half = w & 1, rg = w >> 1;

    for (int i = t; i < BROWS * HH; i += 256) ((float*)scs)[i] = 0.f;

    // qhat registers: cols half*256 + {4*lane..+3, 128+4*lane..+3} for 8 heads
    ulonglong2 qp[HH][2];
    const ulonglong2* qh2 = (const ulonglong2*)g_qhat;  // 128 elems per (b,h) row
#pragma unroll
    for (int h = 0; h < HH; h++) {
        size_t base = ((size_t)b * HH + h) * (DD / 4) + half * 64;
        qp[h][0] = qh2[base + lane];
        qp[h][1] = qh2[base + 32 + lane];
    }
    __syncthreads();

#pragma unroll 2
    for (int i = 0; i < BROWS / 4; i++) {
        int r = rg + 4 * i;
        const ulonglong2* kr =
            (const ulonglong2*)(K + ((size_t)b * LL + l0 + r) * DD + half * 256);
        ulonglong2 k0 = kr[lane];
        ulonglong2 k1 = kr[lane + 32];

        float s[HH];
#pragma unroll
        for (int h = 0; h < HH; h++) {
            unsigned long long a = ffma2u(k0.x, qp[h][0].x, 0ull);
            a = ffma2u(k0.y, qp[h][0].y, a);
            a = ffma2u(k1.x, qp[h][1].x, a);
            a = ffma2u(k1.y, qp[h][1].y, a);
            float x, y;
            unpack2(a, x, y);
            s[h] = x + y;
        }
        // 8-value cross-lane tree reduce (9 shuffles)
#pragma unroll
        for (int j = 0; j < 4; j++) {
            float send = (lane & 16) ? s[j] : s[j + 4];
            float got = __shfl_xor_sync(0xffffffffu, send, 16);
            s[j] = ((lane & 16) ? s[j + 4] : s[j]) + got;
        }
#pragma unroll
        for (int j = 0; j < 2; j++) {
            float send = (lane & 8) ? s[j] : s[j + 2];
            float got = __shfl_xor_sync(0xffffffffu, send, 8);
            s[j] = ((lane & 8) ? s[j + 2] : s[j]) + got;
        }
        {
            float send = (lane & 4) ? s[0] : s[1];
            float got = __shfl_xor_sync(0xffffffffu, send, 4);
            s[0] = ((lane & 4) ? s[1] : s[0]) + got;
        }
        s[0] += __shfl_xor_sync(0xffffffffu, s[0], 2);
        s[0] += __shfl_xor_sync(0xffffffffu, s[0], 1);

        if ((lane & 3) == 0) {
            int h = ((lane >> 2) & 1) | (((lane >> 3) & 1) << 1) | (((lane >> 4) & 1) << 2);
            atomicAdd(&scs[r][h], s[0]);
        }
    }
    __syncthreads();

    const float scale = 0.25f;  // 1/(sqrt(64)*TAU), TAU=0.5
    for (int i = t; i < BROWS * HH; i += 256) {
        int r = i & (BROWS - 1), h = i >> 6;
        float v = (scs[r][h] + g_c[b * HH + h]) * scale;
        g_sc[((size_t)b * HH + h) * LL + l0 + r] = v;
    }
}

// ---------------- kernel C: softmax over l per (b,h) row, in place ----------------
__global__ void k_softmax() {
    int row = blockIdx.x;  // 0..BB*HH-1
    float* p = g_sc + (size_t)row * LL;
    int t = threadIdx.x;  // 256 threads, 32 floats each
    int w = t >> 5, lane = t & 31;

    float4 v[8];
    float m = -1e30f;
#pragma unroll
    for (int i = 0; i < 8; i++) {
        v[i] = ((const float4*)p)[t + 256 * i];
        m = fmaxf(m, fmaxf(fmaxf(v[i].x, v[i].y), fmaxf(v[i].z, v[i].w)));
    }
    __shared__ float red[8];
    for (int o = 16; o > 0; o >>= 1) m = fmaxf(m, __shfl_xor_sync(0xffffffffu, m, o));
    if (lane == 0) red[w] = m;
    __syncthreads();
    m = red[0];
#pragma unroll
    for (int i = 1; i < 8; i++) m = fmaxf(m, red[i]);

    float ssum = 0.f;
#pragma unroll
    for (int i = 0; i < 8; i++) {
        v[i].x = __expf(v[i].x - m);
        v[i].y = __expf(v[i].y - m);
        v[i].z = __expf(v[i].z - m);
        v[i].w = __expf(v[i].w - m);
        ssum += (v[i].x + v[i].y) + (v[i].z + v[i].w);
    }
    __shared__ float red2[8];
    for (int o = 16; o > 0; o >>= 1) ssum += __shfl_xor_sync(0xffffffffu, ssum, o);
    if (lane == 0) red2[w] = ssum;
    __syncthreads();
    ssum = 0.f;
#pragma unroll
    for (int i = 0; i < 8; i++) ssum += red2[i];
    float inv = 1.0f / ssum;
#pragma unroll
    for (int i = 0; i < 8; i++) {
        v[i].x *= inv; v[i].y *= inv; v[i].z *= inv; v[i].w *= inv;
        ((float4*)p)[t + 256 * i] = v[i];
    }
}

// ---------------- kernel D: ctx partials cvp[split,b,h,d] = sum_{l in chunk} w[b,h,l]*V[b,l,d] ----------------
__global__ __launch_bounds__(256, 4) void k_ctx(const float* __restrict__ V) {
    int b = blockIdx.y;
    int split = blockIdx.x;
    int l0 = split * DCHUNK;
    int t = threadIdx.x;

    __shared__ unsigned long long ws[HH * DCHUNK];  // packed (w,w), 8 KB
    __shared__ float comb[128 * 32];                // lh=1 partials, 16 KB

    for (int i = t; i < HH * DCHUNK; i += 256) {
        int h = i >> 7, l = i & (DCHUNK - 1);
        float wv = g_sc[((size_t)b * HH + h) * LL + l0 + l];
        ws[i] = pack2(wv, wv);
    }
    __syncthreads();

    int dq = t & 127, lh = t >> 7;  // thread owns cols 4*dq..4*dq+3; two l per iter
    unsigned long long acc[HH][2];
#pragma unroll
    for (int h = 0; h < HH; h++) { acc[h][0] = 0ull; acc[h][1] = 0ull; }

#pragma unroll 4
    for (int i = 0; i < DCHUNK / 2; i++) {
        int li = 2 * i + lh;
        ulonglong2 v =
            *(const ulonglong2*)(V + ((size_t)b * LL + l0 + li) * DD + 4 * dq);
#pragma unroll
        for (int h = 0; h < HH; h++) {
            unsigned long long wb = ws[h * DCHUNK + li];
            acc[h][0] = ffma2u(wb, v.x, acc[h][0]);
            acc[h][1] = ffma2u(wb, v.y, acc[h][1]);
        }
    }

    if (lh == 1) {
        float* dst = comb + dq * 32;
#pragma unroll
        for (int h = 0; h < HH; h++) {
            unpack2(acc[h][0], dst[h * 4 + 0], dst[h * 4 + 1]);
            unpack2(acc[h][1], dst[h * 4 + 2], dst[h * 4 + 3]);
        }
    }
    __syncthreads();
    if (lh == 0) {
        const float* src = comb + dq * 32;
        float4* out = (float4*)(g_cvp + ((size_t)(split * BB + b)) * HH * DD);
#pragma unroll
        for (int h = 0; h < HH; h++) {
            float x0, y0, x1, y1;
            unpack2(acc[h][0], x0, y0);
            unpack2(acc[h][1], x1, y1);
            out[h * (DD / 4) + dq] = make_float4(x0 + src[h * 4 + 0], y0 + src[h * 4 + 1],
                                                 x1 + src[h * 4 + 2], y1 + src[h * 4 + 3]);
        }
    }
}

// ---------------- kernel E: split-sum + ctx@Wv + @Wo + LN + residual ----------------
__global__ void k_out(const float* __restrict__ Qin, const float* __restrict__ Wv,
                      const float* __restrict__ bv, const float* __restrict__ Wo,
                      const float* __restrict__ bo, const float* __restrict__ gamma,
                      const float* __restrict__ beta, float* __restrict__ out) {
    int b = blockIdx.x;
    int j = threadIdx.x;  // 512 threads
    __shared__ __align__(16) float cvs[HH * DD];  // 16 KB
    __shared__ __align__(16) float ctxs[DD];
    __shared__ float r1[16], r2[16];

    for (int i = j; i < HH * DD; i += DD) {
        float s = 0.f;
#pragma unroll 4
        for (int sp = 0; sp < DSPLITS; sp++)
            s += g_cvp[((size_t)(sp * BB + b)) * HH * DD + i];
        cvs[i] = s;
    }
    __syncthreads();

    int h = j >> 6;
    float acc = bv[j];
#pragma unroll 8
    for (int d = 0; d < DD; d++) acc = fmaf(cvs[h * DD + d], Wv[(size_t)d * DD + j], acc);
    ctxs[j] = acc;
    __syncthreads();

    float o = bo[j];
#pragma unroll 8
    for (int c = 0; c < DD; c++) o = fmaf(ctxs[c], Wo[(size_t)c * DD + j], o);

    float s1 = o, s2 = o * o;
    for (int off = 16; off > 0; off >>= 1) {
        s1 += __shfl_xor_sync(0xffffffffu, s1, off);
        s2 += __shfl_xor_sync(0xffffffffu, s2, off);
    }
    int w = j >> 5, lane = j & 31;
    if (lane == 0) { r1[w] = s1; r2[w] = s2; }
    __syncthreads();
    float mu = 0.f, m2 = 0.f;
#pragma unroll
    for (int i = 0; i < 16; i++) { mu += r1[i]; m2 += r2[i]; }
    mu *= (1.0f / DD);
    float var = m2 * (1.0f / DD) - mu * mu;
    float rstd = rsqrtf(var + LN_EPS);
    out[(size_t)b * DD + j] = (o - mu) * rstd * gamma[j] + beta[j] + Qin[(size_t)b * DD + j];
}

// ---------------- launch ----------------
extern "C" void kernel_launch(void* const* d_in, const int* in_sizes, int n_in,
                              void* d_out, int out_size) {
    const float* Q     = (const float*)d_in[0];
    const float* K     = (const float*)d_in[1];
    const float* V     = (const float*)d_in[2];
    const float* Wq    = (const float*)d_in[3];
    const float* bq    = (const float*)d_in[4];
    const float* Wk    = (const float*)d_in[5];
    const float* bk    = (const float*)d_in[6];
    const float* Wv    = (const float*)d_in[7];
    const float* bv    = (const float*)d_in[8];
    const float* Wo    = (const float*)d_in[9];
    const float* bo    = (const float*)d_in[10];
    const float* gamma = (const float*)d_in[11];
    const float* beta  = (const float*)d_in[12];
    float* out = (float*)d_out;

    k_qproj<<<BB, 512>>>(Q, Wq, bq);
    k_qhat<<<BB, 256>>>(Wk, bk);
    dim3 gb(LL / BROWS, BB);
    k_scores<<<gb, 256>>>(K);
    k_softmax<<<BB * HH, 256>>>();
    dim3 gd(DSPLITS, BB);
    k_ctx<<<gd, 256>>>(V);
    k_out<<<BB, 512>>>(Q, Wv, bv, Wo, bo, gamma, beta, out);
}

// round 3
// speedup vs baseline: 1.1665x; 1.1665x over previous
#include <cuda_runtime.h>
#include <cstdint>
#include <cstddef>

#define BB 16
#define LL 8192
#define DD 512
#define HH 8
#define HD 64
#define LN_EPS 1e-5f

#define BROWS 64
#define DSPLITS 32
#define DCHUNK (LL / DSPLITS) /* 256 */

// ---------------- scratch (device globals; no allocations) ----------------
__device__ __align__(16) float g_q[BB * DD];
__device__ __align__(16) float g_qhat[BB * HH * DD];
__device__ __align__(16) float g_c[BB * HH];
__device__ __align__(16) float g_sc[BB * HH * LL];                 // logits -> weights (in place)
__device__ __align__(16) float g_cvp[DSPLITS * BB * HH * DD];      // ctx partials per split
__device__ __align__(16) float g_ctx2[BB * DD];                    // ctx @ Wv
__device__ __align__(16) float g_o[BB * DD];                       // ctx2 @ Wo (pre-LN)

// ---------------- packed f32x2 helpers ----------------
__device__ __forceinline__ unsigned long long pack2(float x, float y) {
    unsigned long long r;
    asm("mov.b64 %0, {%1, %2};" : "=l"(r) : "f"(x), "f"(y));
    return r;
}
__device__ __forceinline__ void unpack2(unsigned long long v, float& x, float& y) {
    asm("mov.b64 {%0, %1}, %2;" : "=f"(x), "=f"(y) : "l"(v));
}
__device__ __forceinline__ unsigned long long ffma2u(unsigned long long a,
                                                     unsigned long long b,
                                                     unsigned long long c) {
    unsigned long long d;
    asm("fma.rn.f32x2 %0, %1, %2, %3;" : "=l"(d) : "l"(a), "l"(b), "l"(c));
    return d;
}

// ---------------- kernel A1: q[b][j] = Q[b,:]·Wq[:,j] + bq[j] ----------------
// grid (BB, 8): block (b, jc) computes 64 j's; 4 threads per j, 128 d each.
__global__ void k_qproj(const float* __restrict__ Q, const float* __restrict__ Wq,
                        const float* __restrict__ bq) {
    __shared__ __align__(16) float qs[DD];
    __shared__ float part[256];
    int b = blockIdx.x, jc = blockIdx.y;
    int t = threadIdx.x;  // 256
    for (int i = t; i < DD; i += 256) qs[i] = Q[(size_t)b * DD + i];
    __syncthreads();
    int jj = t & 63, seg = t >> 6;
    int j = jc * 64 + jj;
    int d0 = seg * 128;
    float acc = 0.f;
#pragma unroll 16
    for (int dd = 0; dd < 128; dd++)
        acc = fmaf(qs[d0 + dd], Wq[(size_t)(d0 + dd) * DD + j], acc);
    part[t] = acc;
    __syncthreads();
    if (t < 64) {
        float s = part[t] + part[t + 64] + part[t + 128] + part[t + 192] + bq[j];
        g_q[(size_t)b * DD + j] = s;
    }
}

// ---------------- kernel A2: qhat[b,h,d] = sum_hd Wk[d, h*64+hd]*q[b,h,hd]; c[b,h]=q.bk ----------------
// grid (BB, 8): block (b, dc) handles d in [dc*64, dc*64+64); 8 warps, 8 rows each.
__global__ void k_qhat(const float* __restrict__ Wk, const float* __restrict__ bk) {
    __shared__ __align__(16) float qs[DD];
    int b = blockIdx.x, dc = blockIdx.y;
    int t = threadIdx.x;            // 256 threads
    int w = t >> 5, lane = t & 31;  // 8 warps
    for (int i = t; i < DD; i += 256) qs[i] = g_q[(size_t)b * DD + i];
    __syncthreads();

    if (dc == 0) {
        // c[b][w] = sum_i qs[64w+i]*bk[64w+i]
        float s = qs[w * HD + lane] * bk[w * HD + lane] +
                  qs[w * HD + 32 + lane] * bk[w * HD + 32 + lane];
        for (int o = 16; o > 0; o >>= 1) s += __shfl_xor_sync(0xffffffffu, s, o);
        if (lane == 0) g_c[b * HH + w] = s;
    }

    const float4* qs4 = (const float4*)qs;
#pragma unroll
    for (int dl = 0; dl < 8; dl++) {
        int d = dc * 64 + w + 8 * dl;
        const float4* wr = (const float4*)(Wk + (size_t)d * DD);
        float p[4];
#pragma unroll
        for (int j = 0; j < 4; j++) {
            float4 a = wr[lane + 32 * j];
            float4 q4 = qs4[lane + 32 * j];
            p[j] = a.x * q4.x + a.y * q4.y + a.z * q4.z + a.w * q4.w;
        }
#pragma unroll
        for (int j = 0; j < 4; j++) {
            p[j] += __shfl_xor_sync(0xffffffffu, p[j], 1);
            p[j] += __shfl_xor_sync(0xffffffffu, p[j], 2);
            p[j] += __shfl_xor_sync(0xffffffffu, p[j], 4);
            p[j] += __shfl_xor_sync(0xffffffffu, p[j], 8);
        }
        if ((lane & 15) == 0) {
            int hb = lane >> 4;
#pragma unroll
            for (int j = 0; j < 4; j++)
                g_qhat[((size_t)b * HH + 2 * j + hb) * DD + d] = p[j];
        }
    }
}

// ---------------- kernel B: logits[b,h,l] = (K[b,l,:].qhat[b,h,:] + c)/4 ----------------
// 256 threads = 8 warps; warp (half = w&1, rg = w>>1) covers rows rg+4i with 2-deep prefetch.
__global__ __launch_bounds__(256, 2) void k_scores(const float* __restrict__ K) {
    __shared__ float scs[BROWS][HH];
    int b = blockIdx.y;
    int l0 = blockIdx.x * BROWS;
    int t = threadIdx.x, w = t >> 5, lane = t & 31;
    int half = w & 1, rg = w >> 1;

    for (int i = t; i < BROWS * HH; i += 256) ((float*)scs)[i] = 0.f;

    ulonglong2 qp[HH][2];
    const ulonglong2* qh2 = (const ulonglong2*)g_qhat;
#pragma unroll
    for (int h = 0; h < HH; h++) {
        size_t base = ((size_t)b * HH + h) * (DD / 4) + half * 64;
        qp[h][0] = qh2[base + lane];
        qp[h][1] = qh2[base + 32 + lane];
    }
    __syncthreads();

    const float* kbase = K + ((size_t)b * LL + l0) * DD + half * 256;

    // 2-deep prefetch pipeline over 16 rows (r = rg + 4*i)
    ulonglong2 k0a, k1a, k0b, k1b;
    {
        const ulonglong2* kr = (const ulonglong2*)(kbase + (size_t)rg * DD);
        k0a = kr[lane];
        k1a = kr[lane + 32];
        kr = (const ulonglong2*)(kbase + (size_t)(rg + 4) * DD);
        k0b = kr[lane];
        k1b = kr[lane + 32];
    }

#pragma unroll
    for (int i = 0; i < 16; i++) {
        ulonglong2 k0 = k0a, k1 = k1a;
        k0a = k0b; k1a = k1b;
        if (i + 2 < 16) {
            const ulonglong2* kr =
                (const ulonglong2*)(kbase + (size_t)(rg + 4 * (i + 2)) * DD);
            k0b = kr[lane];
            k1b = kr[lane + 32];
        }

        float s[HH];
#pragma unroll
        for (int h = 0; h < HH; h++) {
            unsigned long long a = ffma2u(k0.x, qp[h][0].x, 0ull);
            a = ffma2u(k0.y, qp[h][0].y, a);
            a = ffma2u(k1.x, qp[h][1].x, a);
            a = ffma2u(k1.y, qp[h][1].y, a);
            float x, y;
            unpack2(a, x, y);
            s[h] = x + y;
        }
        // 8-value cross-lane tree reduce (9 shuffles)
#pragma unroll
        for (int j = 0; j < 4; j++) {
            float send = (lane & 16) ? s[j] : s[j + 4];
            float got = __shfl_xor_sync(0xffffffffu, send, 16);
            s[j] = ((lane & 16) ? s[j + 4] : s[j]) + got;
        }
#pragma unroll
        for (int j = 0; j < 2; j++) {
            float send = (lane & 8) ? s[j] : s[j + 2];
            float got = __shfl_xor_sync(0xffffffffu, send, 8);
            s[j] = ((lane & 8) ? s[j + 2] : s[j]) + got;
        }
        {
            float send = (lane & 4) ? s[0] : s[1];
            float got = __shfl_xor_sync(0xffffffffu, send, 4);
            s[0] = ((lane & 4) ? s[1] : s[0]) + got;
        }
        s[0] += __shfl_xor_sync(0xffffffffu, s[0], 2);
        s[0] += __shfl_xor_sync(0xffffffffu, s[0], 1);

        if ((lane & 3) == 0) {
            int h = ((lane >> 2) & 1) | (((lane >> 3) & 1) << 1) | (((lane >> 4) & 1) << 2);
            atomicAdd(&scs[rg + 4 * i][h], s[0]);
        }
    }
    __syncthreads();

    const float scale = 0.25f;  // 1/(sqrt(64)*TAU), TAU=0.5
    for (int i = t; i < BROWS * HH; i += 256) {
        int r = i & (BROWS - 1), h = i >> 6;
        float v = (scs[r][h] + g_c[b * HH + h]) * scale;
        g_sc[((size_t)b * HH + h) * LL + l0 + r] = v;
    }
}

// ---------------- kernel C: softmax over l per (b,h) row, in place ----------------
__global__ void k_softmax() {
    int row = blockIdx.x;  // 0..BB*HH-1
    float* p = g_sc + (size_t)row * LL;
    int t = threadIdx.x;  // 256 threads, 32 floats each
    int w = t >> 5, lane = t & 31;

    float4 v[8];
    float m = -1e30f;
#pragma unroll
    for (int i = 0; i < 8; i++) {
        v[i] = ((const float4*)p)[t + 256 * i];
        m = fmaxf(m, fmaxf(fmaxf(v[i].x, v[i].y), fmaxf(v[i].z, v[i].w)));
    }
    __shared__ float red[8];
    for (int o = 16; o > 0; o >>= 1) m = fmaxf(m, __shfl_xor_sync(0xffffffffu, m, o));
    if (lane == 0) red[w] = m;
    __syncthreads();
    m = red[0];
#pragma unroll
    for (int i = 1; i < 8; i++) m = fmaxf(m, red[i]);

    float ssum = 0.f;
#pragma unroll
    for (int i = 0; i < 8; i++) {
        v[i].x = __expf(v[i].x - m);
        v[i].y = __expf(v[i].y - m);
        v[i].z = __expf(v[i].z - m);
        v[i].w = __expf(v[i].w - m);
        ssum += (v[i].x + v[i].y) + (v[i].z + v[i].w);
    }
    __shared__ float red2[8];
    for (int o = 16; o > 0; o >>= 1) ssum += __shfl_xor_sync(0xffffffffu, ssum, o);
    if (lane == 0) red2[w] = ssum;
    __syncthreads();
    ssum = 0.f;
#pragma unroll
    for (int i = 0; i < 8; i++) ssum += red2[i];
    float inv = 1.0f / ssum;
#pragma unroll
    for (int i = 0; i < 8; i++) {
        v[i].x *= inv; v[i].y *= inv; v[i].z *= inv; v[i].w *= inv;
        ((float4*)p)[t + 256 * i] = v[i];
    }
}

// ---------------- kernel D: ctx partials cvp[split,b,h,d] = sum_{l in chunk} w[b,h,l]*V[b,l,d] ----------------
__global__ __launch_bounds__(256, 4) void k_ctx(const float* __restrict__ V) {
    int b = blockIdx.y;
    int split = blockIdx.x;
    int l0 = split * DCHUNK;
    int t = threadIdx.x;

    __shared__ unsigned long long ws[HH * DCHUNK];  // packed (w,w), 16 KB
    __shared__ float comb[128 * 32];                // lh=1 partials, 16 KB

    for (int i = t; i < HH * DCHUNK; i += 256) {
        int h = i >> 8, l = i & (DCHUNK - 1);
        float wv = g_sc[((size_t)b * HH + h) * LL + l0 + l];
        ws[i] = pack2(wv, wv);
    }
    __syncthreads();

    int dq = t & 127, lh = t >> 7;  // thread owns cols 4*dq..4*dq+3; two l per iter
    unsigned long long acc[HH][2];
#pragma unroll
    for (int h = 0; h < HH; h++) { acc[h][0] = 0ull; acc[h][1] = 0ull; }

    const float* vptr = V + ((size_t)b * LL + l0 + lh) * DD + 4 * dq;
    ulonglong2 vc = *(const ulonglong2*)vptr;

#pragma unroll 4
    for (int i = 0; i < DCHUNK / 2 - 1; i++) {
        ulonglong2 vn = *(const ulonglong2*)(vptr + (size_t)(i + 1) * 2 * DD);
        int li = 2 * i + lh;
#pragma unroll
        for (int h = 0; h < HH; h++) {
            unsigned long long wb = ws[h * DCHUNK + li];
            acc[h][0] = ffma2u(wb, vc.x, acc[h][0]);
            acc[h][1] = ffma2u(wb, vc.y, acc[h][1]);
        }
        vc = vn;
    }
    {
        int li = DCHUNK - 2 + lh;
#pragma unroll
        for (int h = 0; h < HH; h++) {
            unsigned long long wb = ws[h * DCHUNK + li];
            acc[h][0] = ffma2u(wb, vc.x, acc[h][0]);
            acc[h][1] = ffma2u(wb, vc.y, acc[h][1]);
        }
    }

    if (lh == 1) {
        float* dst = comb + dq * 32;
#pragma unroll
        for (int h = 0; h < HH; h++) {
            unpack2(acc[h][0], dst[h * 4 + 0], dst[h * 4 + 1]);
            unpack2(acc[h][1], dst[h * 4 + 2], dst[h * 4 + 3]);
        }
    }
    __syncthreads();
    if (lh == 0) {
        const float* src = comb + dq * 32;
        float4* out = (float4*)(g_cvp + ((size_t)(split * BB + b)) * HH * DD);
#pragma unroll
        for (int h = 0; h < HH; h++) {
            float x0, y0, x1, y1;
            unpack2(acc[h][0], x0, y0);
            unpack2(acc[h][1], x1, y1);
            out[h * (DD / 4) + dq] = make_float4(x0 + src[h * 4 + 0], y0 + src[h * 4 + 1],
                                                 x1 + src[h * 4 + 2], y1 + src[h * 4 + 3]);
        }
    }
}

// ---------------- kernel E1: ctx2[b][h*64+jj] = (sum_sp cvp)[h,:]·Wv[:,j] + bv[j] ----------------
// grid (BB, HH)
__global__ void k_proj_wv(const float* __restrict__ Wv, const float* __restrict__ bv) {
    __shared__ __align__(16) float cvs[DD];
    __shared__ float part[256];
    int b = blockIdx.x, h = blockIdx.y;
    int t = threadIdx.x;  // 256

    for (int d = t; d < DD; d += 256) {
        float s = 0.f;
#pragma unroll 8
        for (int sp = 0; sp < DSPLITS; sp++)
            s += g_cvp[((size_t)(sp * BB + b) * HH + h) * DD + d];
        cvs[d] = s;
    }
    __syncthreads();

    int jj = t & 63, seg = t >> 6;
    int j = h * 64 + jj;
    int d0 = seg * 128;
    float acc = 0.f;
#pragma unroll 16
    for (int dd = 0; dd < 128; dd++)
        acc = fmaf(cvs[d0 + dd], Wv[(size_t)(d0 + dd) * DD + j], acc);
    part[t] = acc;
    __syncthreads();
    if (t < 64) {
        float s = part[t] + part[t + 64] + part[t + 128] + part[t + 192] + bv[j];
        g_ctx2[(size_t)b * DD + j] = s;
    }
}

// ---------------- kernel E2: o[b][j] = ctx2[b,:]·Wo[:,j] + bo[j] ----------------
// grid (BB, 8)
__global__ void k_proj_wo(const float* __restrict__ Wo, const float* __restrict__ bo) {
    __shared__ __align__(16) float cs[DD];
    __shared__ float part[256];
    int b = blockIdx.x, jc = blockIdx.y;
    int t = threadIdx.x;  // 256
    for (int i = t; i < DD; i += 256) cs[i] = g_ctx2[(size_t)b * DD + i];
    __syncthreads();

    int jj = t & 63, seg = t >> 6;
    int j = jc * 64 + jj;
    int d0 = seg * 128;
    float acc = 0.f;
#pragma unroll 16
    for (int dd = 0; dd < 128; dd++)
        acc = fmaf(cs[d0 + dd], Wo[(size_t)(d0 + dd) * DD + j], acc);
    part[t] = acc;
    __syncthreads();
    if (t < 64) {
        float s = part[t] + part[t + 64] + part[t + 128] + part[t + 192] + bo[j];
        g_o[(size_t)b * DD + j] = s;
    }
}

// ---------------- kernel E3: LN + residual ----------------
__global__ void k_ln(const float* __restrict__ Qin, const float* __restrict__ gamma,
                     const float* __restrict__ beta, float* __restrict__ out) {
    int b = blockIdx.x;
    int j = threadIdx.x;  // 512
    __shared__ float r1[16], r2[16];
    float o = g_o[(size_t)b * DD + j];

    float s1 = o, s2 = o * o;
    for (int off = 16; off > 0; off >>= 1) {
        s1 += __shfl_xor_sync(0xffffffffu, s1, off);
        s2 += __shfl_xor_sync(0xffffffffu, s2, off);
    }
    int w = j >> 5, lane = j & 31;
    if (lane == 0) { r1[w] = s1; r2[w] = s2; }
    __syncthreads();
    float mu = 0.f, m2 = 0.f;
#pragma unroll
    for (int i = 0; i < 16; i++) { mu += r1[i]; m2 += r2[i]; }
    mu *= (1.0f / DD);
    float var = m2 * (1.0f / DD) - mu * mu;
    float rstd = rsqrtf(var + LN_EPS);
    out[(size_t)b * DD + j] = (o - mu) * rstd * gamma[j] + beta[j] + Qin[(size_t)b * DD + j];
}

// ---------------- launch ----------------
extern "C" void kernel_launch(void* const* d_in, const int* in_sizes, int n_in,
                              void* d_out, int out_size) {
    const float* Q     = (const float*)d_in[0];
    const float* K     = (const float*)d_in[1];
    const float* V     = (const float*)d_in[2];
    const float* Wq    = (const float*)d_in[3];
    const float* bq    = (const float*)d_in[4];
    const float* Wk    = (const float*)d_in[5];
    const float* bk    = (const float*)d_in[6];
    const float* Wv    = (const float*)d_in[7];
    const float* bv    = (const float*)d_in[8];
    const float* Wo    = (const float*)d_in[9];
    const float* bo    = (const float*)d_in[10];
    const float* gamma = (const float*)d_in[11];
    const float* beta  = (const float*)d_in[12];
    float* out = (float*)d_out;

    dim3 g16x8(BB, 8);
    k_qproj<<<g16x8, 256>>>(Q, Wq, bq);
    k_qhat<<<g16x8, 256>>>(Wk, bk);
    dim3 gb(LL / BROWS, BB);
    k_scores<<<gb, 256>>>(K);
    k_softmax<<<BB * HH, 256>>>();
    dim3 gd(DSPLITS, BB);
    k_ctx<<<gd, 256>>>(V);
    dim3 ge(BB, HH);
    k_proj_wv<<<ge, 256>>>(Wv, bv);
    k_proj_wo<<<g16x8, 256>>>(Wo, bo);
    k_ln<<<BB, 512>>>(Q, gamma, beta, out);
}